// round 4
// baseline (speedup 1.0000x reference)
#include <cuda_runtime.h>
#include <cuda_bf16.h>

// CompetitiveLayer: 21 iterations of
//   AF = AT / (1 + K @ BF)        (row matvec,   K = param^2)
//   BF = BT / (1 + AF @ K)        (col matvec)
// then C = K * AF[:,None] * BF[None,:]
//
// N = 4096. K (64 MB fp32) is L2-resident after the first pass; the kernel
// sequence is tuned to stream K from L2 at full LTS throughput.

#define N        4096
#define NF4      (N / 4)          // 1024 float4 per row
#define NITER    21
#define ROW_CHUNKS 8              // col-matvec row split (deterministic 2-stage reduce)
#define CHUNK_ROWS (N / ROW_CHUNKS)   // 512

// Scratch (no cudaMalloc allowed)
__device__ float g_AF[N];
__device__ float g_BF[N];
__device__ float g_tmp[ROW_CHUNKS * N];

// ---------------------------------------------------------------------------
// Row matvec: AF[i] = AT[i] / (1 + sum_j param[i][j]^2 * BF[j])
// 1 warp per row, 8 rows per 256-thread block, BF staged in shared once/block.
// grid = 512 blocks.
// ---------------------------------------------------------------------------
__global__ __launch_bounds__(256, 2)
void row_mv_kernel(const float* __restrict__ P,
                   const float* __restrict__ AT,
                   const float* __restrict__ BT,
                   int use_bt)
{
    __shared__ float4 sBF[NF4];   // 16 KB

    const int tid  = threadIdx.x;
    const float* BFin = use_bt ? BT : g_BF;
    const float4* bf4 = reinterpret_cast<const float4*>(BFin);

    #pragma unroll
    for (int i = tid; i < NF4; i += 256) sBF[i] = bf4[i];
    __syncthreads();

    const int warp = tid >> 5;
    const int lane = tid & 31;
    const int row  = blockIdx.x * 8 + warp;

    const float4* prow = reinterpret_cast<const float4*>(P + ((size_t)row << 12));

    float4 acc = make_float4(0.f, 0.f, 0.f, 0.f);
    #pragma unroll 8
    for (int j = lane; j < NF4; j += 32) {
        float4 p = prow[j];
        float4 b = sBF[j];
        acc.x = fmaf(p.x * p.x, b.x, acc.x);
        acc.y = fmaf(p.y * p.y, b.y, acc.y);
        acc.z = fmaf(p.z * p.z, b.z, acc.z);
        acc.w = fmaf(p.w * p.w, b.w, acc.w);
    }
    float s = (acc.x + acc.y) + (acc.z + acc.w);
    #pragma unroll
    for (int o = 16; o > 0; o >>= 1) s += __shfl_xor_sync(0xFFFFFFFFu, s, o);

    if (lane == 0) g_AF[row] = AT[row] / (1.0f + s);
}

// ---------------------------------------------------------------------------
// Col matvec partial: tmp[chunk][j] = sum_{i in chunk} AF[i] * param[i][j]^2
// grid = (32 col-tiles of 128 cols, 8 row-chunks of 512 rows) = 256 blocks.
// Block: 8 warps = 8 row lanes; each lane owns 4 consecutive cols via float4.
// ---------------------------------------------------------------------------
__global__ __launch_bounds__(256, 2)
void col_mv_partial_kernel(const float* __restrict__ P)
{
    __shared__ float  sAF[CHUNK_ROWS];      // 2 KB
    __shared__ float4 sAcc[8][32];          // 4 KB

    const int tid     = threadIdx.x;
    const int warp    = tid >> 5;
    const int lane    = tid & 31;
    const int colBase = blockIdx.x * 128;
    const int rowBase = blockIdx.y * CHUNK_ROWS;

    for (int i = tid; i < CHUNK_ROWS; i += 256) sAF[i] = g_AF[rowBase + i];
    __syncthreads();

    float4 acc = make_float4(0.f, 0.f, 0.f, 0.f);
    #pragma unroll 4
    for (int k = 0; k < CHUNK_ROWS / 8; k++) {
        const int r = warp + 8 * k;               // 0..511, per-warp row stream
        const float a = sAF[r];
        const float4 p = *reinterpret_cast<const float4*>(
            P + (((size_t)(rowBase + r)) << 12) + colBase + 4 * lane);
        acc.x = fmaf(a * p.x, p.x, acc.x);
        acc.y = fmaf(a * p.y, p.y, acc.y);
        acc.z = fmaf(a * p.z, p.z, acc.z);
        acc.w = fmaf(a * p.w, p.w, acc.w);
    }
    sAcc[warp][lane] = acc;
    __syncthreads();

    // Deterministic cross-warp reduce: thread t (<128) owns col colBase+t.
    // Flattened float index inside sAcc[w] equals the in-tile col index.
    if (tid < 128) {
        float s = 0.f;
        #pragma unroll
        for (int w = 0; w < 8; w++) {
            const float* rowv = reinterpret_cast<const float*>(sAcc[w]);
            s += rowv[tid];
        }
        g_tmp[blockIdx.y * N + colBase + tid] = s;
    }
}

// ---------------------------------------------------------------------------
// Finalize: BF[j] = BT[j] / (1 + sum_chunks tmp[chunk][j]).  grid = 16 x 256.
// ---------------------------------------------------------------------------
__global__ __launch_bounds__(256, 4)
void finalize_bf_kernel(const float* __restrict__ BT)
{
    const int j = blockIdx.x * 256 + threadIdx.x;
    float s = 0.f;
    #pragma unroll
    for (int c = 0; c < ROW_CHUNKS; c++) s += g_tmp[c * N + j];
    g_BF[j] = BT[j] / (1.0f + s);
}

// ---------------------------------------------------------------------------
// Output: C[i][j] = param[i][j]^2 * AF[i] * BF[j].  One float4 per thread.
// grid = 16384 x 256.
// ---------------------------------------------------------------------------
__global__ __launch_bounds__(256, 4)
void compute_c_kernel(const float* __restrict__ P, float* __restrict__ C)
{
    const size_t idx = (size_t)blockIdx.x * 256 + threadIdx.x;  // float4 index
    const int row  = (int)(idx >> 10);          // /1024 float4 per row
    const int col4 = (int)(idx & 1023);

    const float a  = g_AF[row];
    const float4 p = reinterpret_cast<const float4*>(P)[idx];
    const float4 b = *reinterpret_cast<const float4*>(&g_BF[col4 * 4]);

    float4 o;
    o.x = p.x * p.x * a * b.x;
    o.y = p.y * p.y * a * b.y;
    o.z = p.z * p.z * a * b.z;
    o.w = p.w * p.w * a * b.w;
    reinterpret_cast<float4*>(C)[idx] = o;
}

// ---------------------------------------------------------------------------
// Launch: 21 x {rowMV, colMV-partial, finalize} + C.  64 graph nodes, all on
// the default stream (graph-capturable; no sync, no alloc, no memcpy).
// ---------------------------------------------------------------------------
extern "C" void kernel_launch(void* const* d_in, const int* in_sizes, int n_in,
                              void* d_out, int out_size)
{
    const float* AT = (const float*)d_in[0];   // [4096]
    const float* BT = (const float*)d_in[1];   // [4096]
    const float* P  = (const float*)d_in[2];   // [4096, 4096]
    float* C = (float*)d_out;                  // [4096, 4096]

    const dim3 colGrid(N / 128, ROW_CHUNKS);   // (32, 8)

    for (int it = 0; it < NITER; it++) {
        row_mv_kernel<<<N / 8, 256>>>(P, AT, BT, it == 0 ? 1 : 0);
        col_mv_partial_kernel<<<colGrid, 256>>>(P);
        finalize_bf_kernel<<<N / 256, 256>>>(BT);
    }
    compute_c_kernel<<<(N * NF4) / 256, 256>>>(P, C);
}